// round 3
// baseline (speedup 1.0000x reference)
#include <cuda_runtime.h>

// SinusoidalEmbedding: out[b][s][d] = emb_table[x[b][s]][d] + PE[s][d]
// PE[s][2i] = sin(s*f_i), PE[s][2i+1] = cos(s*f_i), f_i = 10000^(-2i/1024)
//
// R3: same flat layout (one CTA per position, 256 threads, one float4/thread),
// but: (a) all 8 batch gathers issued back-to-back into registers BEFORE any
// store -> per-thread MLP=8 (R2's regs=32 proved ptxas serialized them);
// (b) stores use .cs (evict-first) so the 128MB write stream doesn't evict
// gathered emb rows from L2 -> duplicate-row gathers stay L2 hits.

#define D_M4    256      // D_M/4
#define BQ      8
#define S_LEN   4096

__device__ __forceinline__ void stcs4(float4* p, float4 v) {
    asm volatile("st.global.cs.v4.f32 [%0], {%1,%2,%3,%4};"
                 :: "l"(p), "f"(v.x), "f"(v.y), "f"(v.z), "f"(v.w) : "memory");
}

__global__ __launch_bounds__(256, 5)
void sinemb_kernel(const void* __restrict__ xraw,
                   const float* __restrict__ emb,
                   float* __restrict__ out)
{
    const int t = threadIdx.x;          // float4 index within D: d = 4t..4t+3
    const int s = blockIdx.x;           // position

    // ---- index dtype detect (int64 vs int32), uniform broadcast loads ----
    const unsigned int* w = (const unsigned int*)xraw;
    const bool is64 = ((w[1] | w[3] | w[5] | w[7]) == 0u);

    // ---- gather rows for this position across the batch (uniform per CTA) ----
    int rows[BQ];
    if (is64) {
        const long long* x64 = (const long long*)xraw;
        #pragma unroll
        for (int b = 0; b < BQ; b++) rows[b] = (int)x64[(long long)b * S_LEN + s];
    } else {
        const int* x32 = (const int*)xraw;
        #pragma unroll
        for (int b = 0; b < BQ; b++) rows[b] = x32[b * S_LEN + s];
    }

    // ---- issue all 8 gathers back-to-back: MLP = 8 per thread ----
    const float4* emb4 = (const float4*)emb;
    float4 e[BQ];
    #pragma unroll
    for (int b = 0; b < BQ; b++)
        e[b] = __ldg(&emb4[(long long)rows[b] * D_M4 + t]);

    // ---- positional encoding for this thread's float4 (overlaps load latency) ----
    // f_i = 2^(c_exp * i), c_exp = -2*log2(10000)/1024
    const float c_exp = -0.02595256324130752f;
    const float fs = (float)s;
    float f0 = exp2f(c_exp * (float)(2 * t));
    float f1 = exp2f(c_exp * (float)(2 * t + 1));
    float4 p;
    sincosf(fs * f0, &p.x, &p.y);
    sincosf(fs * f1, &p.z, &p.w);

    // ---- add + streaming store (evict-first: don't pollute L2) ----
    float4* out4 = (float4*)out;
    #pragma unroll
    for (int b = 0; b < BQ; b++) {
        float4 o;
        o.x = e[b].x + p.x; o.y = e[b].y + p.y;
        o.z = e[b].z + p.z; o.w = e[b].w + p.w;
        stcs4(&out4[((long long)b * S_LEN + s) * D_M4 + t], o);
    }
}

extern "C" void kernel_launch(void* const* d_in, const int* in_sizes, int n_in,
                              void* d_out, int out_size)
{
    const void*  x   = d_in[0];                 // [8, 4096] int64 (or int32)
    const float* emb = (const float*)d_in[1];   // [50257, 1024] fp32
    float*       out = (float*)d_out;           // [8, 4096, 1024] fp32

    sinemb_kernel<<<S_LEN, 256>>>(x, emb, out);
}

// round 4
// speedup vs baseline: 1.0787x; 1.0787x over previous
#include <cuda_runtime.h>

// SinusoidalEmbedding: out[b][s][d] = emb_table[x[b][s]][d] + PE[s][d]
// PE[s][2i] = sin(s*f_i), PE[s][2i+1] = cos(s*f_i), f_i = 10000^(-2i/1024)
//
// R4: R2 flat layout (one CTA per position, 256 threads, one float4/thread,
// plain stores — R3 proved .cs stores regress). Single change vs R2:
// 2-stage load pipeline — batch 4 gathers, compute PE under their latency,
// store them, batch the next 4, store. regs ~40 -> ~6 CTAs/SM, per-thread
// MLP=4 instead of R2's ~1-2.

#define D_M4    256      // D_M/4
#define BQ      8
#define S_LEN   4096

__global__ __launch_bounds__(256)
void sinemb_kernel(const void* __restrict__ xraw,
                   const float* __restrict__ emb,
                   float* __restrict__ out)
{
    const int t = threadIdx.x;          // float4 index within D: d = 4t..4t+3
    const int s = blockIdx.x;           // position

    // ---- index dtype detect (int64 vs int32), uniform broadcast loads ----
    const unsigned int* w = (const unsigned int*)xraw;
    const bool is64 = ((w[1] | w[3] | w[5] | w[7]) == 0u);

    // ---- gather rows for this position across the batch (uniform per CTA) ----
    int rows[BQ];
    if (is64) {
        const long long* x64 = (const long long*)xraw;
        #pragma unroll
        for (int b = 0; b < BQ; b++) rows[b] = (int)x64[(long long)b * S_LEN + s];
    } else {
        const int* x32 = (const int*)xraw;
        #pragma unroll
        for (int b = 0; b < BQ; b++) rows[b] = x32[b * S_LEN + s];
    }

    const float4* emb4 = (const float4*)emb;
    float4*       out4 = (float4*)out;

    // ---- group 0: issue 4 gathers back-to-back (MLP=4) ----
    float4 e0[4];
    #pragma unroll
    for (int b = 0; b < 4; b++)
        e0[b] = __ldg(&emb4[(long long)rows[b] * D_M4 + t]);

    // ---- PE for this thread's float4 (hidden under group-0 load latency) ----
    // f_i = 2^(c_exp * i), c_exp = -2*log2(10000)/1024
    const float c_exp = -0.02595256324130752f;
    const float fs = (float)s;
    float f0 = exp2f(c_exp * (float)(2 * t));
    float f1 = exp2f(c_exp * (float)(2 * t + 1));
    float4 p;
    sincosf(fs * f0, &p.x, &p.y);
    sincosf(fs * f1, &p.z, &p.w);

    // ---- store group 0 ----
    #pragma unroll
    for (int b = 0; b < 4; b++) {
        float4 o;
        o.x = e0[b].x + p.x; o.y = e0[b].y + p.y;
        o.z = e0[b].z + p.z; o.w = e0[b].w + p.w;
        out4[((long long)b * S_LEN + s) * D_M4 + t] = o;
    }

    // ---- group 1: issue 4 gathers back-to-back, then store ----
    float4 e1[4];
    #pragma unroll
    for (int b = 0; b < 4; b++)
        e1[b] = __ldg(&emb4[(long long)rows[4 + b] * D_M4 + t]);

    #pragma unroll
    for (int b = 0; b < 4; b++) {
        float4 o;
        o.x = e1[b].x + p.x; o.y = e1[b].y + p.y;
        o.z = e1[b].z + p.z; o.w = e1[b].w + p.w;
        out4[((long long)(4 + b) * S_LEN + s) * D_M4 + t] = o;
    }
}

extern "C" void kernel_launch(void* const* d_in, const int* in_sizes, int n_in,
                              void* d_out, int out_size)
{
    const void*  x   = d_in[0];                 // [8, 4096] int64 (or int32)
    const float* emb = (const float*)d_in[1];   // [50257, 1024] fp32
    float*       out = (float*)d_out;           // [8, 4096, 1024] fp32

    sinemb_kernel<<<S_LEN, 256>>>(x, emb, out);
}